// round 8
// baseline (speedup 1.0000x reference)
#include <cuda_runtime.h>

// T=2048, B=4096, P=512, NA=2, 7 fields/row.
#define TT 2048
#define BB 4096
#define NF 7
#define CHUNK 16            // timesteps per chunk
#define CC 128              // TT / CHUNK
#define CB (CC * BB)        // 524288 (chunk, column) pairs
#define THREADS 256

// Decoupled-lookback scratch (device globals; flags cleared per launch).
// agg planes 0..5:  A,B (egr affine), dha, cumB, nhB, tipB   (transform of chunk)
// inc planes 6..9:  egr,cum,nh,tip inclusive state after chunk
__device__ float    g_pay[10 * CB];
__device__ unsigned g_flag[CB];      // 0 = none, 1 = aggregate ready, 2 = inclusive ready

__device__ __forceinline__ float sigmoidf_(float x) { return 1.0f / (1.0f + expf(-x)); }
__device__ __forceinline__ float softplusf_(float x) { return log1pf(expf(x)); }

// ── clear flags each launch (graph-replay safe) ──
__global__ void __launch_bounds__(256)
mvt_clear()
{
    reinterpret_cast<uint4*>(g_flag)[blockIdx.x * 256 + threadIdx.x] =
        make_uint4(0, 0, 0, 0);
}

__global__ void __launch_bounds__(THREADS, 5)
mvt_main(const float* __restrict__ inp,
         const float* __restrict__ ar_, const float* __restrict__ br_,
         const float* __restrict__ cr_, const float* __restrict__ dr_,
         const float* __restrict__ gr_,
         float* __restrict__ out)
{
    extern __shared__ float2 sPQ[];           // [CHUNK][THREADS] = 32 KB

    const int tid  = threadIdx.x;
    const int j    = blockIdx.x >> 4;         // chunk id 0..127 (low blocks = low j)
    const int bgrp = blockIdx.x & 15;
    const int b    = bgrp * THREADS + tid;    // column
    const int idx  = j * BB + b;

    // per-column params
    const int   pid   = (int)inp[(size_t)b * NF + 6];
    const float alpha = fminf(fmaxf(sigmoidf_(ar_[pid]), 0.01f), 0.99f);
    const float beta  = fminf(fmaxf(softplusf_(br_[pid]), 0.1f), 10.0f);
    const float c     = fminf(fmaxf(cr_[pid], -10.0f), 10.0f);
    const float depl  = fminf(fmaxf(softplusf_(dr_[pid]), 0.001f), 1.0f);
    const float base  = fminf(fmaxf(softplusf_(gr_[pid]), 0.1f), 20.0f);
    const float l2a   = log2f(1.0f - alpha);
    const float bd    = beta * depl;

    const float*  p   = inp + (size_t)b * NF;
    const size_t  STR = (size_t)BB * NF;
    const int     t0  = j * CHUNK;

    // cts entering this chunk: function of input row t0-1 only (or base for j==0)
    float cts_prev = base;
    if (j != 0) {
        const float* q = p + (size_t)(t0 - 1) * STR;
        cts_prev = (q[0] != 0.0f) ? (q[2] + q[3]) : base;
    }

    // ── Phase A: chunk-local transforms; (P,Q) into smem ──
    float A = 1.0f, Bc = 0.0f;                // egr_{t-1} = A*egr_entry + Bc
    float dha = 1.0f, cumB = 0.0f, nhB = 0.0f, tipB = 0.0f;

#pragma unroll 4
    for (int i = 0; i < CHUNK; ++i) {
        const float* q = p + (size_t)(t0 + i) * STR;
        const float dh = q[0];                // exactly 0.0f or 1.0f
        const float r0 = q[2], r1 = q[3];
        const float hd = q[4], td = q[5];

        const float bh = beta * hd;
        const float P  = c + fmaf(bd, cts_prev, -(bh * Bc));
        const float Q  = -(bh * A);
        sPQ[i * THREADS + tid] = make_float2(P, Q);

        const float ar  = r0 + r1;
        const float ts  = fmaf(dh, hd - td, td);
        const float av  = exp2f(ts * l2a);    // (1-alpha)^ts
        const float obs = __fdividef(ar, ts + 1e-8f);

        Bc = fmaf(av, Bc, (1.0f - av) * obs);
        A *= av;
        cumB = (cumB + ar)  * dh;
        nhB  = (nhB + 1.0f) * dh;
        tipB = (tipB + ts)  * dh;
        dha *= dh;
        cts_prev = (dh != 0.0f) ? ar : base;
    }

    // publish aggregate (payload, fence, release flag=1)
    if (j != 0) {
        g_pay[0 * CB + idx] = A;
        g_pay[1 * CB + idx] = Bc;
        g_pay[2 * CB + idx] = dha;
        g_pay[3 * CB + idx] = cumB;
        g_pay[4 * CB + idx] = nhB;
        g_pay[5 * CB + idx] = tipB;
        __threadfence();
        *((volatile unsigned*)&g_flag[idx]) = 1u;
    }

    // ── Phase B: decoupled lookback with inclusive early-termination ──
    float Ra = 1.0f, Rb = 0.0f;               // composed applied-later transform (egr)
    float Rd = 1.0f, Rc = 0.0f, Rn = 0.0f, Rt = 0.0f;
    float egr0 = base, cum0 = 0.0f, nh0 = 0.0f, tip0 = 0.0f;   // entry state

    for (int k = j - 1; k >= 0; --k) {
        const int kk = k * BB + b;
        unsigned f;
        for (;;) {
            f = *((volatile unsigned*)&g_flag[kk]);
            if (f) break;
            __nanosleep(50);
        }
        __threadfence();                      // acquire: payload after flag
        if (f == 2u) {
            const float Se = *((volatile float*)&g_pay[6 * CB + kk]);
            const float Sc = *((volatile float*)&g_pay[7 * CB + kk]);
            const float Sn = *((volatile float*)&g_pay[8 * CB + kk]);
            const float St = *((volatile float*)&g_pay[9 * CB + kk]);
            egr0 = fmaf(Ra, Se, Rb);
            cum0 = fmaf(Rd, Sc, Rc);
            nh0  = fmaf(Rd, Sn, Rn);
            tip0 = fmaf(Rd, St, Rt);
            break;
        }
        const float TA = *((volatile float*)&g_pay[0 * CB + kk]);
        const float TB = *((volatile float*)&g_pay[1 * CB + kk]);
        const float Td = *((volatile float*)&g_pay[2 * CB + kk]);
        const float Tc = *((volatile float*)&g_pay[3 * CB + kk]);
        const float Tn = *((volatile float*)&g_pay[4 * CB + kk]);
        const float Tt = *((volatile float*)&g_pay[5 * CB + kk]);
        Rb = fmaf(Ra, TB, Rb);  Ra *= TA;     // R = R ∘ T_k
        Rc = fmaf(Rd, Tc, Rc);
        Rn = fmaf(Rd, Tn, Rn);
        Rt = fmaf(Rd, Tt, Rt);
        Rd *= Td;
        if (k == 0) {                          // reached the start: apply R to init state
            egr0 = fmaf(Ra, base, Rb);
            cum0 = Rc; nh0 = Rn; tip0 = Rt;
        }
    }

    // inclusive state after chunk j; publish (flag=2) so successors stop here
    const float egrI = fmaf(A, egr0, Bc);
    const float cumI = fmaf(dha, cum0, cumB);
    const float nhI  = fmaf(dha, nh0,  nhB);
    const float tipI = fmaf(dha, tip0, tipB);
    if (j != CC - 1) {
        g_pay[6 * CB + idx] = egrI;
        g_pay[7 * CB + idx] = cumI;
        g_pay[8 * CB + idx] = nhI;
        g_pay[9 * CB + idx] = tipI;
        __threadfence();
        *((volatile unsigned*)&g_flag[idx]) = 2u;
    }

    // ── Phase C: write logits straight from smem ──
    float2* __restrict__ o2 = reinterpret_cast<float2*>(out) + b;
#pragma unroll 4
    for (int i = 0; i < CHUNK; ++i) {
        const float2 pq = sPQ[i * THREADS + tid];
        o2[(size_t)(t0 + i) * BB] = make_float2(fmaf(pq.y, egr0, pq.x), 0.0f);
    }

    // ── finals: last chunk owns the full-column state ──
    if (j == CC - 1) {
        float* fin = out + (size_t)TT * BB * 2;
        fin[b]          = cumI;
        fin[BB + b]     = nhI;
        fin[2 * BB + b] = tipI;
        fin[3 * BB + b] = egrI;
        fin[4 * BB + b] = cts_prev;           // cts at t = T-1
    }
}

extern "C" void kernel_launch(void* const* d_in, const int* in_sizes, int n_in,
                              void* d_out, int out_size)
{
    (void)in_sizes; (void)n_in; (void)out_size;
    const float* inp  = (const float*)d_in[0];
    const float* araw = (const float*)d_in[1];
    const float* braw = (const float*)d_in[2];
    const float* craw = (const float*)d_in[3];
    const float* draw = (const float*)d_in[4];
    const float* graw = (const float*)d_in[5];

    cudaFuncSetAttribute(mvt_main,
                         cudaFuncAttributeMaxDynamicSharedMemorySize,
                         CHUNK * THREADS * sizeof(float2));

    mvt_clear<<<CB / (256 * 4), 256>>>();
    mvt_main<<<CC * (BB / THREADS), THREADS, CHUNK * THREADS * sizeof(float2)>>>(
        inp, araw, braw, craw, draw, graw, (float*)d_out);
}

// round 9
// speedup vs baseline: 1.1534x; 1.1534x over previous
#include <cuda_runtime.h>

// T=2048, B=4096, P=512, NA=2, 7 fields/row.
#define TT 2048
#define BB 4096
#define NF 7
#define CHUNK 32            // timesteps per chunk
#define CC 64               // TT / CHUNK
#define CB (CC * BB)        // 262144 (chunk, column) pairs
#define THREADS 256

// Decoupled-lookback scratch (device globals; flags cleared per launch).
__device__ float4   g_agg4[CB];      // (A, Bc, dha, cumB)   chunk transform
__device__ float2   g_agg2[CB];      // (nhB, tipB)
__device__ float4   g_inc4[CB];      // (egr, cum, nh, tip)  inclusive state after chunk
__device__ unsigned g_flag[CB];      // 0 none, 1 aggregate ready, 2 inclusive ready

__device__ __forceinline__ float sigmoidf_(float x) { return 1.0f / (1.0f + expf(-x)); }
__device__ __forceinline__ float softplusf_(float x) { return log1pf(expf(x)); }

// ── clear flags each launch (graph-replay safe) ──
__global__ void __launch_bounds__(256)
mvt_clear()
{
    reinterpret_cast<uint4*>(g_flag)[blockIdx.x * 256 + threadIdx.x] =
        make_uint4(0, 0, 0, 0);
}

__global__ void __launch_bounds__(THREADS, 3)
mvt_main(const float* __restrict__ inp,
         const float* __restrict__ ar_, const float* __restrict__ br_,
         const float* __restrict__ cr_, const float* __restrict__ dr_,
         const float* __restrict__ gr_,
         float* __restrict__ out)
{
    extern __shared__ float2 sPQ[];           // [CHUNK][THREADS] = 64 KB

    const int tid  = threadIdx.x;
    const int j    = blockIdx.x >> 4;         // chunk id 0..63 (low blocks = low j)
    const int bgrp = blockIdx.x & 15;
    const int b    = bgrp * THREADS + tid;    // column
    const int idx  = j * BB + b;

    // per-column params
    const int   pid   = (int)inp[(size_t)b * NF + 6];
    const float alpha = fminf(fmaxf(sigmoidf_(ar_[pid]), 0.01f), 0.99f);
    const float beta  = fminf(fmaxf(softplusf_(br_[pid]), 0.1f), 10.0f);
    const float c     = fminf(fmaxf(cr_[pid], -10.0f), 10.0f);
    const float depl  = fminf(fmaxf(softplusf_(dr_[pid]), 0.001f), 1.0f);
    const float base  = fminf(fmaxf(softplusf_(gr_[pid]), 0.1f), 20.0f);
    const float l2a   = log2f(1.0f - alpha);
    const float bd    = beta * depl;

    const float*  p   = inp + (size_t)b * NF;
    const size_t  STR = (size_t)BB * NF;
    const int     t0  = j * CHUNK;

    // cts entering this chunk: function of input row t0-1 only (or base for j==0)
    float cts_prev = base;
    if (j != 0) {
        const float* q = p + (size_t)(t0 - 1) * STR;
        cts_prev = (q[0] != 0.0f) ? (q[2] + q[3]) : base;
    }

    // ── Phase A: chunk-local transforms; (P,Q) into smem ──
    float A = 1.0f, Bc = 0.0f;                // egr_{t-1} = A*egr_entry + Bc
    float dha = 1.0f, cumB = 0.0f, nhB = 0.0f, tipB = 0.0f;

#pragma unroll 4
    for (int i = 0; i < CHUNK; ++i) {
        const float* q = p + (size_t)(t0 + i) * STR;
        const float dh = q[0];                // exactly 0.0f or 1.0f
        const float r0 = q[2], r1 = q[3];
        const float hd = q[4], td = q[5];

        const float bh = beta * hd;
        const float P  = c + fmaf(bd, cts_prev, -(bh * Bc));
        const float Q  = -(bh * A);
        sPQ[i * THREADS + tid] = make_float2(P, Q);

        const float ar  = r0 + r1;
        const float ts  = fmaf(dh, hd - td, td);
        const float av  = exp2f(ts * l2a);    // (1-alpha)^ts
        const float obs = __fdividef(ar, ts + 1e-8f);

        Bc = fmaf(av, Bc, (1.0f - av) * obs);
        A *= av;
        cumB = (cumB + ar)  * dh;
        nhB  = (nhB + 1.0f) * dh;
        tipB = (tipB + ts)  * dh;
        dha *= dh;
        cts_prev = (dh != 0.0f) ? ar : base;
    }

    // publish aggregate (payload .cg, fence, release flag=1)
    if (j != 0) {
        __stcg(&g_agg4[idx], make_float4(A, Bc, dha, cumB));
        __stcg(&g_agg2[idx], make_float2(nhB, tipB));
        __threadfence();
        *((volatile unsigned*)&g_flag[idx]) = 1u;
    }

    // ── Phase B: batched decoupled lookback with inclusive early-exit ──
    float Ra = 1.0f, Rb = 0.0f;               // composed applied-later transform (egr)
    float Rd = 1.0f, Rc = 0.0f, Rn = 0.0f, Rt = 0.0f;
    float egr0 = base, cum0 = 0.0f, nh0 = 0.0f, tip0 = 0.0f;   // entry state of chunk j

    bool done = (j == 0);
    for (int k = j - 1; !done; ) {
        const int m = (k >= 3) ? 4 : (k + 1);
        unsigned f0, f1 = 1, f2 = 1, f3 = 1;
        for (;;) {                             // 4 independent flag probes per spin
            f0 = *((volatile unsigned*)&g_flag[k * BB + b]);
            if (m > 1) f1 = *((volatile unsigned*)&g_flag[(k - 1) * BB + b]);
            if (m > 2) f2 = *((volatile unsigned*)&g_flag[(k - 2) * BB + b]);
            if (m > 3) f3 = *((volatile unsigned*)&g_flag[(k - 3) * BB + b]);
            if (f0 && f1 && f2 && f3) break;
            __nanosleep(50);
        }
        __threadfence();                       // acquire: payloads after flags
        const unsigned fl[4] = { f0, f1, f2, f3 };
#pragma unroll
        for (int u = 0; u < 4; ++u) {
            if (u >= m) break;
            const int kk = (k - u) * BB + b;
            if (fl[u] == 2u) {                 // inclusive: apply R and stop
                const float4 S = __ldcg(&g_inc4[kk]);
                egr0 = fmaf(Ra, S.x, Rb);
                cum0 = fmaf(Rd, S.y, Rc);
                nh0  = fmaf(Rd, S.z, Rn);
                tip0 = fmaf(Rd, S.w, Rt);
                done = true;
                break;
            }
            const float4 T4 = __ldcg(&g_agg4[kk]);   // A,Bc,dha,cumB
            const float2 T2 = __ldcg(&g_agg2[kk]);   // nhB,tipB
            Rb = fmaf(Ra, T4.y, Rb);  Ra *= T4.x;    // R = R ∘ T_k
            Rc = fmaf(Rd, T4.w, Rc);
            Rn = fmaf(Rd, T2.x, Rn);
            Rt = fmaf(Rd, T2.y, Rt);
            Rd *= T4.z;
            if (k - u == 0) {                  // reached the start: apply init state
                egr0 = fmaf(Ra, base, Rb);
                cum0 = Rc; nh0 = Rn; tip0 = Rt;
                done = true;
                break;
            }
        }
        k -= m;
    }

    // inclusive state after chunk j; publish (flag=2) so successors stop here
    const float egrI = fmaf(A, egr0, Bc);
    const float cumI = fmaf(dha, cum0, cumB);
    const float nhI  = fmaf(dha, nh0,  nhB);
    const float tipI = fmaf(dha, tip0, tipB);
    if (j != CC - 1) {
        __stcg(&g_inc4[idx], make_float4(egrI, cumI, nhI, tipI));
        __threadfence();
        *((volatile unsigned*)&g_flag[idx]) = 2u;
    }

    // ── Phase C: write logits straight from smem ──
    float2* __restrict__ o2 = reinterpret_cast<float2*>(out) + b;
#pragma unroll 4
    for (int i = 0; i < CHUNK; ++i) {
        const float2 pq = sPQ[i * THREADS + tid];
        o2[(size_t)(t0 + i) * BB] = make_float2(fmaf(pq.y, egr0, pq.x), 0.0f);
    }

    // ── finals: last chunk owns the full-column state ──
    if (j == CC - 1) {
        float* fin = out + (size_t)TT * BB * 2;
        fin[b]          = cumI;
        fin[BB + b]     = nhI;
        fin[2 * BB + b] = tipI;
        fin[3 * BB + b] = egrI;
        fin[4 * BB + b] = cts_prev;           // cts at t = T-1
    }
}

extern "C" void kernel_launch(void* const* d_in, const int* in_sizes, int n_in,
                              void* d_out, int out_size)
{
    (void)in_sizes; (void)n_in; (void)out_size;
    const float* inp  = (const float*)d_in[0];
    const float* araw = (const float*)d_in[1];
    const float* braw = (const float*)d_in[2];
    const float* craw = (const float*)d_in[3];
    const float* draw = (const float*)d_in[4];
    const float* graw = (const float*)d_in[5];

    cudaFuncSetAttribute(mvt_main,
                         cudaFuncAttributeMaxDynamicSharedMemorySize,
                         CHUNK * THREADS * sizeof(float2));

    mvt_clear<<<CB / (256 * 4), 256>>>();
    mvt_main<<<CC * (BB / THREADS), THREADS, CHUNK * THREADS * sizeof(float2)>>>(
        inp, araw, braw, craw, draw, graw, (float*)d_out);
}